// round 1
// baseline (speedup 1.0000x reference)
#include <cuda_runtime.h>
#include <cstdint>
#include <cstdio>

// ---------------------------------------------------------------------------
// Problem constants (fixed by the dataset)
// ---------------------------------------------------------------------------
#define E_MAX 262144
#define T_MAX 2097152
#define D_ 128
#define DA_ 64

// ---------------------------------------------------------------------------
// Scratch (device globals -- no allocation allowed)
// ---------------------------------------------------------------------------
__device__ float g_h1  [(size_t)E_MAX * 128];  // 128 MB
__device__ float g_ang [(size_t)E_MAX * 64];   //  64 MB
__device__ float g_agg [(size_t)E_MAX * 64];   //  64 MB
__device__ float g_t   [(size_t)E_MAX * 128];  // 128 MB
__device__ float g_m   [(size_t)E_MAX * 128];  // 128 MB
__device__ float g_rbf8[(size_t)E_MAX * 8];    //   8 MB
__device__ float g_sbf8[(size_t)T_MAX * 8];    //  64 MB

// ---------------------------------------------------------------------------
// Epilogue modes
// ---------------------------------------------------------------------------
#define EP_SWISH      0
#define EP_SWISH_MULG 1   // out = swish(acc+bias) * (row8 @ Wg)[col]
#define EP_SWISH_ADD  2   // out = swish(acc+bias) + addend[row,col]

__device__ __forceinline__ float swishf(float v) {
    return v / (1.0f + __expf(-v));
}

// ---------------------------------------------------------------------------
// Tiled SGEMM:  C[M x BN] = epilogue(A[M x K] @ B[K x BN])
// BM=128, BK=16, 256 threads, TMxTN register microtile.
// Grid.x = M / BM.  N must equal BN (weights are narrow).
// ---------------------------------------------------------------------------
#define BM 128
#define BK 16

template<int BN, int TM, int TN, int MODE>
__global__ __launch_bounds__(256) void gemm_kernel(
    const float* __restrict__ A,
    const float* __restrict__ B,
    const float* __restrict__ bias,   // may be null
    const float* __restrict__ extra,  // addend (EP_SWISH_ADD) or Wg [8 x BN] (EP_SWISH_MULG)
    const float* __restrict__ row8,   // [M x 8] (EP_SWISH_MULG)
    float* __restrict__ C,
    int K)
{
    __shared__ float As[BK][BM];
    __shared__ float Bs[BK][BN];

    const int tid      = threadIdx.x;
    const int blockRow = blockIdx.x;
    constexpr int NTC  = BN / TN;   // threads per row of C tile (16)
    const int tRow = tid / NTC;
    const int tCol = tid % NTC;

    float acc[TM][TN];
    #pragma unroll
    for (int i = 0; i < TM; i++)
        #pragma unroll
        for (int j = 0; j < TN; j++) acc[i][j] = 0.0f;

    const float* Ab = A + (size_t)blockRow * BM * K;

    for (int kt = 0; kt < K; kt += BK) {
        // A tile: BM x BK (stored transposed)
        #pragma unroll
        for (int i = tid; i < BM * BK / 4; i += 256) {
            int r  = i / (BK / 4);
            int c4 = (i % (BK / 4)) * 4;
            float4 v = *reinterpret_cast<const float4*>(Ab + (size_t)r * K + kt + c4);
            As[c4 + 0][r] = v.x;
            As[c4 + 1][r] = v.y;
            As[c4 + 2][r] = v.z;
            As[c4 + 3][r] = v.w;
        }
        // B tile: BK x BN
        #pragma unroll
        for (int i = tid; i < BK * BN / 4; i += 256) {
            int r  = i / (BN / 4);
            int c4 = (i % (BN / 4)) * 4;
            *reinterpret_cast<float4*>(&Bs[r][c4]) =
                *reinterpret_cast<const float4*>(B + (size_t)(kt + r) * BN + c4);
        }
        __syncthreads();

        #pragma unroll
        for (int k = 0; k < BK; k++) {
            float ra[TM], rb[TN];
            #pragma unroll
            for (int i = 0; i < TM; i++) ra[i] = As[k][tRow * TM + i];
            #pragma unroll
            for (int j = 0; j < TN; j++) rb[j] = Bs[k][tCol * TN + j];
            #pragma unroll
            for (int i = 0; i < TM; i++)
                #pragma unroll
                for (int j = 0; j < TN; j++)
                    acc[i][j] = fmaf(ra[i], rb[j], acc[i][j]);
        }
        __syncthreads();
    }

    // Epilogue
    #pragma unroll
    for (int i = 0; i < TM; i++) {
        const int row = blockRow * BM + tRow * TM + i;
        float r8[8];
        if (MODE == EP_SWISH_MULG) {
            #pragma unroll
            for (int b = 0; b < 8; b++) r8[b] = row8[(size_t)row * 8 + b];
        }
        #pragma unroll
        for (int j = 0; j < TN; j++) {
            const int col = tCol * TN + j;
            float v = acc[i][j];
            if (bias) v += bias[col];
            float sv = swishf(v);
            if (MODE == EP_SWISH_MULG) {
                float g = 0.0f;
                #pragma unroll
                for (int b = 0; b < 8; b++)
                    g = fmaf(r8[b], extra[b * BN + col], g);
                sv *= g;
            } else if (MODE == EP_SWISH_ADD) {
                sv += extra[(size_t)row * BN + col];
            }
            C[(size_t)row * BN + col] = sv;
        }
    }
}

// ---------------------------------------------------------------------------
// proj8: out[rows x 8] = X[rows x NIN] @ W[NIN x 8]
// smem-staged for fully coalesced global reads.
// ---------------------------------------------------------------------------
template<int NIN>
__global__ __launch_bounds__(256) void proj8_kernel(
    const float* __restrict__ X, const float* __restrict__ W,
    float* __restrict__ out)
{
    __shared__ float tile[256 * NIN];
    __shared__ float Ws[NIN * 8];
    const size_t base = (size_t)blockIdx.x * 256;
    for (int i = threadIdx.x; i < 256 * NIN; i += 256)
        tile[i] = X[base * NIN + i];
    for (int i = threadIdx.x; i < NIN * 8; i += 256)
        Ws[i] = W[i];
    __syncthreads();

    const float* x = &tile[threadIdx.x * NIN];
    float o[8] = {0, 0, 0, 0, 0, 0, 0, 0};
    #pragma unroll
    for (int c = 0; c < NIN; c++) {
        float xv = x[c];
        #pragma unroll
        for (int b = 0; b < 8; b++)
            o[b] = fmaf(xv, Ws[c * 8 + b], o[b]);
    }
    float4* op = reinterpret_cast<float4*>(out + (base + threadIdx.x) * 8);
    op[0] = make_float4(o[0], o[1], o[2], o[3]);
    op[1] = make_float4(o[4], o[5], o[6], o[7]);
}

// ---------------------------------------------------------------------------
// zero fill
// ---------------------------------------------------------------------------
__global__ void zero_kernel(float4* __restrict__ p, size_t n4)
{
    size_t i = (size_t)blockIdx.x * blockDim.x + threadIdx.x;
    if (i < n4) p[i] = make_float4(0.f, 0.f, 0.f, 0.f);
}

// ---------------------------------------------------------------------------
// Triplet gather/gate/scatter:
//   for each triplet t:  agg[reduce[t], :] += ang[expand[t], :] * (sbf8[t] @ Wsbf2)
// 16 lanes per triplet, 4 columns per lane, vector red.add.
// ---------------------------------------------------------------------------
__global__ __launch_bounds__(256) void triplet_kernel(
    const int* __restrict__ expand_to_kj,
    const int* __restrict__ reduce_to_ji,
    const float* __restrict__ sbf8,     // [T x 8]
    const float* __restrict__ Wsbf2,    // [8 x 64]
    const float* __restrict__ ang,      // [E x 64]
    float* __restrict__ agg)            // [E x 64]
{
    __shared__ float Ws[8 * 64];
    for (int i = threadIdx.x; i < 512; i += 256) Ws[i] = Wsbf2[i];
    __syncthreads();

    const int lane16 = threadIdx.x & 15;
    const size_t tIdx = ((size_t)blockIdx.x * 256 + threadIdx.x) >> 4;

    const int ekj = expand_to_kj[tIdx];
    const int eji = reduce_to_ji[tIdx];
    const float* s8 = sbf8 + tIdx * 8;

    float g0 = 0.f, g1 = 0.f, g2 = 0.f, g3 = 0.f;
    #pragma unroll
    for (int b = 0; b < 8; b++) {
        const float sb = __ldg(&s8[b]);   // broadcast across half-warp
        const float* w = &Ws[b * 64 + lane16 * 4];
        g0 = fmaf(sb, w[0], g0);
        g1 = fmaf(sb, w[1], g1);
        g2 = fmaf(sb, w[2], g2);
        g3 = fmaf(sb, w[3], g3);
    }

    float4 a = __ldg(reinterpret_cast<const float4*>(ang + (size_t)ekj * 64 + lane16 * 4));
    float vx = a.x * g0, vy = a.y * g1, vz = a.z * g2, vw = a.w * g3;

    float* dst = agg + (size_t)eji * 64 + lane16 * 4;
    asm volatile("red.global.add.v4.f32 [%0], {%1,%2,%3,%4};"
                 :: "l"(dst), "f"(vx), "f"(vy), "f"(vz), "f"(vw)
                 : "memory");
}

// ---------------------------------------------------------------------------
// Host orchestration
// ---------------------------------------------------------------------------
extern "C" void kernel_launch(void* const* d_in, const int* in_sizes, int n_in,
                              void* d_out, int out_size)
{
    const float* m_input = (const float*)d_in[0];
    const float* rbf     = (const float*)d_in[1];
    const float* sbf     = (const float*)d_in[2];
    const int*   expand  = (const int*)  d_in[3];
    const int*   reduce  = (const int*)  d_in[4];
    const float* W_kj    = (const float*)d_in[5];
    const float* b_kj    = (const float*)d_in[6];
    const float* W_rbf1  = (const float*)d_in[7];
    const float* W_rbf2  = (const float*)d_in[8];
    const float* W_sbf1  = (const float*)d_in[9];
    const float* W_sbf2  = (const float*)d_in[10];
    const float* W_down  = (const float*)d_in[11];
    const float* W_up    = (const float*)d_in[12];
    const float* W_ji    = (const float*)d_in[13];
    const float* b_ji    = (const float*)d_in[14];
    const float* W_res_b = (const float*)d_in[15];
    const float* b_res_b = (const float*)d_in[16];
    const float* W_final = (const float*)d_in[17];
    const float* b_final = (const float*)d_in[18];
    const float* W_res_a = (const float*)d_in[19];
    const float* b_res_a = (const float*)d_in[20];
    float* out = (float*)d_out;

    const int E = in_sizes[0] / 128;   // 262144
    const int T = in_sizes[3];         // 2097152

    float *h1, *ang, *agg, *t, *m, *rbf8, *sbf8;
    cudaGetSymbolAddress((void**)&h1,   g_h1);
    cudaGetSymbolAddress((void**)&ang,  g_ang);
    cudaGetSymbolAddress((void**)&agg,  g_agg);
    cudaGetSymbolAddress((void**)&t,    g_t);
    cudaGetSymbolAddress((void**)&m,    g_m);
    cudaGetSymbolAddress((void**)&rbf8, g_rbf8);
    cudaGetSymbolAddress((void**)&sbf8, g_sbf8);

    const int GE = E / BM;             // 2048 blocks per big GEMM

    // 1. rbf8 = rbf @ W_rbf1                              [E,8]
    proj8_kernel<6><<<E / 256, 256>>>(rbf, W_rbf1, rbf8);

    // 2. h1 = swish(m_input @ W_kj + b_kj) * (rbf8 @ W_rbf2)   [E,128]
    gemm_kernel<128, 8, 8, EP_SWISH_MULG><<<GE, 256>>>(
        m_input, W_kj, b_kj, W_rbf2, rbf8, h1, 128);

    // 3. ang = swish(h1 @ W_down)                         [E,64]
    gemm_kernel<64, 8, 4, EP_SWISH><<<GE, 256>>>(
        h1, W_down, nullptr, nullptr, nullptr, ang, 128);

    // 4. sbf8 = sbf @ W_sbf1                              [T,8]
    proj8_kernel<42><<<T / 256, 256>>>(sbf, W_sbf1, sbf8);

    // 5. agg = 0
    {
        size_t n4 = (size_t)E * 64 / 4;
        zero_kernel<<<(unsigned)((n4 + 255) / 256), 256>>>((float4*)agg, n4);
    }

    // 6. scatter: agg[reduce[t]] += ang[expand[t]] * (sbf8[t] @ W_sbf2)
    triplet_kernel<<<(unsigned)((size_t)T * 16 / 256), 256>>>(
        expand, reduce, sbf8, W_sbf2, ang, agg);

    // 7. t = swish(agg @ W_up)                            [E,128]  (propagated)
    gemm_kernel<128, 8, 8, EP_SWISH><<<GE, 256>>>(
        agg, W_up, nullptr, nullptr, nullptr, t, 64);

    // 8. m = swish(m_input @ W_ji + b_ji) + t
    gemm_kernel<128, 8, 8, EP_SWISH_ADD><<<GE, 256>>>(
        m_input, W_ji, b_ji, t, nullptr, m, 128);

    // 9. residual block (before skip): 1 layer, 2 sublayers
    gemm_kernel<128, 8, 8, EP_SWISH><<<GE, 256>>>(
        m, W_res_b, b_res_b, nullptr, nullptr, h1, 128);
    gemm_kernel<128, 8, 8, EP_SWISH_ADD><<<GE, 256>>>(
        h1, W_res_b + 128 * 128, b_res_b + 128, m, nullptr, t, 128);   // t = new m

    // 10. m = swish(t @ W_final + b_final) + m_input
    gemm_kernel<128, 8, 8, EP_SWISH_ADD><<<GE, 256>>>(
        t, W_final, b_final, m_input, nullptr, m, 128);

    // 11. residual block (after skip): 2 layers
    gemm_kernel<128, 8, 8, EP_SWISH><<<GE, 256>>>(
        m, W_res_a, b_res_a, nullptr, nullptr, h1, 128);
    gemm_kernel<128, 8, 8, EP_SWISH_ADD><<<GE, 256>>>(
        h1, W_res_a + 128 * 128, b_res_a + 128, m, nullptr, t, 128);   // t = m

    gemm_kernel<128, 8, 8, EP_SWISH><<<GE, 256>>>(
        t, W_res_a + 2 * 128 * 128, b_res_a + 256, nullptr, nullptr, h1, 128);
    gemm_kernel<128, 8, 8, EP_SWISH_ADD><<<GE, 256>>>(
        h1, W_res_a + 3 * 128 * 128, b_res_a + 384, t, nullptr, out, 128);
}

// round 3
// speedup vs baseline: 1.3475x; 1.3475x over previous
#include <cuda_runtime.h>
#include <cuda_bf16.h>
#include <cstdint>

// ---------------------------------------------------------------------------
// Problem constants
// ---------------------------------------------------------------------------
#define E_MAX 262144
#define T_MAX 2097152

// ---------------------------------------------------------------------------
// Scratch (device globals -- no allocation allowed)
// ---------------------------------------------------------------------------
__device__ float g_h1  [(size_t)E_MAX * 128];
__device__ float g_ang [(size_t)E_MAX * 64];
__device__ float g_agg [(size_t)E_MAX * 64];
__device__ float g_t   [(size_t)E_MAX * 128];
__device__ float g_m   [(size_t)E_MAX * 128];
__device__ float g_rbf8[(size_t)E_MAX * 8];
__device__ float g_sbf8[(size_t)T_MAX * 8];
__device__ float g_wb  [163840];   // 640KB: pre-converted bf16 hi/lo weight fragments

#define EP_SWISH      0
#define EP_SWISH_MULG 1
#define EP_SWISH_ADD  2

__device__ __forceinline__ float swishf(float v) { return v / (1.0f + __expf(-v)); }

__device__ __forceinline__ uint32_t smem_u32(const void* p) {
    uint32_t a;
    asm("{ .reg .u64 t; cvta.to.shared.u64 t, %1; cvt.u32.u64 %0, t; }"
        : "=r"(a) : "l"(p));
    return a;
}

// ldmatrix x4: 16x16 bf16 tile -> A fragment regs (m16n8k16 order)
__device__ __forceinline__ void ldm_x4(uint32_t* r, uint32_t addr) {
    asm volatile("ldmatrix.sync.aligned.m8n8.x4.shared.b16 {%0,%1,%2,%3}, [%4];"
                 : "=r"(r[0]), "=r"(r[1]), "=r"(r[2]), "=r"(r[3]) : "r"(addr));
}

// mma.sync m16n8k16 bf16 -> f32 accumulate
__device__ __forceinline__ void mma_bf16(float* d, const uint32_t* a, uint32_t b0, uint32_t b1) {
    asm volatile("mma.sync.aligned.m16n8k16.row.col.f32.bf16.bf16.f32 "
                 "{%0,%1,%2,%3}, {%4,%5,%6,%7}, {%8,%9}, {%0,%1,%2,%3};"
                 : "+f"(d[0]), "+f"(d[1]), "+f"(d[2]), "+f"(d[3])
                 : "r"(a[0]), "r"(a[1]), "r"(a[2]), "r"(a[3]), "r"(b0), "r"(b1));
}

// ---------------------------------------------------------------------------
// Weight pre-conversion: W[K,N] f32 row-major -> hi/lo bf16 in the exact
// per-thread B-fragment layout of mma.m16n8k16 (col operand):
//   element (k, n):  ks=k/16, kin=k%16, n8=n/8, nin=n%8
//   lane = nin*4 + (kin&7)/2 ; reg = kin/8 ; half = kin&1
//   u32 index = ((n8*KST + ks)*32 + lane)*2 + reg
// hi buffer at offset 0, lo buffer at N*K bf16 elements.
// ---------------------------------------------------------------------------
__global__ void wconv_kernel(const float* __restrict__ W, float* __restrict__ dst,
                             int K, int N)
{
    __nv_bfloat16* d16 = (__nv_bfloat16*)dst;
    const int KST = K >> 4;
    const int loOff = N * K;
    for (int i = threadIdx.x + blockIdx.x * blockDim.x; i < K * N;
         i += blockDim.x * gridDim.x) {
        int k = i / N, n = i % N;
        float v = W[i];
        __nv_bfloat16 h = __float2bfloat16_rn(v);
        __nv_bfloat16 l = __float2bfloat16_rn(v - __bfloat162float(h));
        int ks = k >> 4, kin = k & 15, n8 = n >> 3, nin = n & 7;
        int lane = nin * 4 + ((kin & 7) >> 1);
        int reg  = kin >> 3;
        int half = kin & 1;
        int idx16 = ((((n8 * KST + ks) * 32 + lane) * 2 + reg) << 1) + half;
        d16[idx16] = h;
        d16[loOff + idx16] = l;
    }
}

// ---------------------------------------------------------------------------
// HMMA GEMM: C[E x N] = epilogue(A[E x K] @ W[K x N]), fp32 in/out.
// 3-term bf16 split: Ahi*Bhi + Ahi*Blo + Alo*Bhi, fp32 register accumulators.
// CTA: 128 rows x N cols, 256 threads, warp tile 32 x N/2.
// ---------------------------------------------------------------------------
template<int N, int K, int MODE>
__global__ __launch_bounds__(256) void mma_gemm(
    const float*    __restrict__ A,
    const uint32_t* __restrict__ Bpre,   // fragment-layout bf16 hi|lo
    const float*    __restrict__ bias,   // may be null
    const float*    __restrict__ extra,  // addend [E,N] (ADD) or Wg [8,N] (MULG)
    const float*    __restrict__ row8,   // [E,8] (MULG)
    float*          __restrict__ C)
{
    constexpr int KST  = K / 16;
    constexpr int WN   = N / 2;          // warp N tile
    constexpr int N8   = WN / 8;         // B fragments per warp in N
    constexpr int LDA  = K + 8;          // bf16 elems per smem row (conflict-free)
    constexpr int ABYT = 128 * LDA * 2;  // bytes per A precision buffer
    constexpr int BTERM = N * K / 2;     // u32 per B precision buffer

    extern __shared__ __align__(16) char smem[];
    float* sbias = (float*)smem;                       // 512 B
    float* sWg   = (float*)(smem + 512);               // 4 KB max
    char*  AhiB  = smem + 4608;
    char*  AloB  = AhiB + ABYT;

    const int tid = threadIdx.x, wid = tid >> 5, lane = tid & 31;
    const size_t rowBase = (size_t)blockIdx.x * 128;

    // --- stage bias / gate weights ---
    if (bias)
        for (int i = tid; i < N; i += 256) sbias[i] = bias[i];
    if (MODE == EP_SWISH_MULG)
        for (int i = tid; i < 8 * N; i += 256) sWg[i] = extra[i];

    // --- stage A: f32 -> bf16 hi/lo in smem ---
    {
        const float4* Ab = (const float4*)(A + rowBase * K);
        constexpr int NF4 = 128 * K / 4;
        #pragma unroll 4
        for (int i = tid; i < NF4; i += 256) {
            int r  = i / (K / 4);
            int c4 = (i % (K / 4)) * 4;
            float4 v = Ab[i];
            __nv_bfloat162 h01, h23, l01, l23;
            h01.x = __float2bfloat16_rn(v.x);
            h01.y = __float2bfloat16_rn(v.y);
            h23.x = __float2bfloat16_rn(v.z);
            h23.y = __float2bfloat16_rn(v.w);
            l01.x = __float2bfloat16_rn(v.x - __bfloat162float(h01.x));
            l01.y = __float2bfloat16_rn(v.y - __bfloat162float(h01.y));
            l23.x = __float2bfloat16_rn(v.z - __bfloat162float(h23.x));
            l23.y = __float2bfloat16_rn(v.w - __bfloat162float(h23.y));
            uint2 hv, lv;
            hv.x = *(uint32_t*)&h01; hv.y = *(uint32_t*)&h23;
            lv.x = *(uint32_t*)&l01; lv.y = *(uint32_t*)&l23;
            size_t off = (size_t)r * LDA * 2 + (size_t)c4 * 2;
            *(uint2*)(AhiB + off) = hv;
            *(uint2*)(AloB + off) = lv;
        }
    }
    __syncthreads();

    // --- main loop ---
    const int warpM = (wid & 3) * 32;
    const int warpN = (wid >> 2) * WN;

    float acc[2][N8][4];
    #pragma unroll
    for (int m = 0; m < 2; m++)
        #pragma unroll
        for (int j = 0; j < N8; j++)
            #pragma unroll
            for (int q = 0; q < 4; q++) acc[m][j][q] = 0.0f;

    // ldmatrix base addresses for this lane (row = warpM + m*16 + (lane&15))
    const uint32_t aHiAddr = smem_u32(AhiB) +
        (uint32_t)(warpM + (lane & 15)) * (LDA * 2) + (uint32_t)(lane >> 4) * 16;
    const uint32_t aLoAddr = aHiAddr + (uint32_t)ABYT;

    #pragma unroll
    for (int term = 0; term < 3; term++) {
        const uint32_t aBase = (term == 2) ? aLoAddr : aHiAddr;
        const uint32_t* Bp = Bpre + ((term == 1) ? BTERM : 0);
        #pragma unroll
        for (int ks = 0; ks < KST; ks++) {
            uint32_t afr[2][4];
            ldm_x4(afr[0], aBase + ks * 32);
            ldm_x4(afr[1], aBase + 16 * (LDA * 2) + ks * 32);
            #pragma unroll
            for (int j = 0; j < N8; j++) {
                const int n8g = (warpN >> 3) + j;
                uint2 b = *(const uint2*)(Bp + ((size_t)(n8g * KST + ks) * 32 + lane) * 2);
                mma_bf16(acc[0][j], afr[0], b.x, b.y);
                mma_bf16(acc[1][j], afr[1], b.x, b.y);
            }
        }
    }

    // --- epilogue: c0,c1 -> row lane/4 ; c2,c3 -> row lane/4+8 ---
    const int r0 = lane >> 2;
    const int c0 = (lane & 3) * 2;

    #pragma unroll
    for (int m = 0; m < 2; m++) {
        const int rowA = warpM + m * 16 + r0;
        const int rowB = rowA + 8;
        const size_t gA = rowBase + rowA;
        const size_t gB = rowBase + rowB;

        float r8A[8], r8B[8];
        if (MODE == EP_SWISH_MULG) {
            float4 a0 = *(const float4*)(row8 + gA * 8);
            float4 a1 = *(const float4*)(row8 + gA * 8 + 4);
            float4 b0 = *(const float4*)(row8 + gB * 8);
            float4 b1 = *(const float4*)(row8 + gB * 8 + 4);
            r8A[0]=a0.x; r8A[1]=a0.y; r8A[2]=a0.z; r8A[3]=a0.w;
            r8A[4]=a1.x; r8A[5]=a1.y; r8A[6]=a1.z; r8A[7]=a1.w;
            r8B[0]=b0.x; r8B[1]=b0.y; r8B[2]=b0.z; r8B[3]=b0.w;
            r8B[4]=b1.x; r8B[5]=b1.y; r8B[6]=b1.z; r8B[7]=b1.w;
        }

        #pragma unroll
        for (int j = 0; j < N8; j++) {
            const int col = warpN + j * 8 + c0;
            float v0 = acc[m][j][0], v1 = acc[m][j][1];
            float v2 = acc[m][j][2], v3 = acc[m][j][3];
            if (bias) {
                float b0 = sbias[col], b1 = sbias[col + 1];
                v0 += b0; v1 += b1; v2 += b0; v3 += b1;
            }
            v0 = swishf(v0); v1 = swishf(v1);
            v2 = swishf(v2); v3 = swishf(v3);
            if (MODE == EP_SWISH_MULG) {
                float gA0 = 0.f, gA1 = 0.f, gB0 = 0.f, gB1 = 0.f;
                #pragma unroll
                for (int b = 0; b < 8; b++) {
                    float w0 = sWg[b * N + col], w1 = sWg[b * N + col + 1];
                    gA0 = fmaf(r8A[b], w0, gA0);
                    gA1 = fmaf(r8A[b], w1, gA1);
                    gB0 = fmaf(r8B[b], w0, gB0);
                    gB1 = fmaf(r8B[b], w1, gB1);
                }
                v0 *= gA0; v1 *= gA1; v2 *= gB0; v3 *= gB1;
            } else if (MODE == EP_SWISH_ADD) {
                float2 eA = *(const float2*)(extra + gA * N + col);
                float2 eB = *(const float2*)(extra + gB * N + col);
                v0 += eA.x; v1 += eA.y; v2 += eB.x; v3 += eB.y;
            }
            *(float2*)(C + gA * N + col) = make_float2(v0, v1);
            *(float2*)(C + gB * N + col) = make_float2(v2, v3);
        }
    }
}

// ---------------------------------------------------------------------------
// proj8: out[rows x 8] = X[rows x NIN] @ W[NIN x 8]  (float4 staging)
// ---------------------------------------------------------------------------
template<int NIN>
__global__ __launch_bounds__(256) void proj8_kernel(
    const float* __restrict__ X, const float* __restrict__ W,
    float* __restrict__ out)
{
    __shared__ float tile[256 * NIN];
    __shared__ float Ws[NIN * 8];
    const size_t base = (size_t)blockIdx.x * 256;
    constexpr int NT4 = 256 * NIN / 4;
    const float4* src = (const float4*)(X + base * NIN);
    #pragma unroll 4
    for (int i = threadIdx.x; i < NT4; i += 256)
        ((float4*)tile)[i] = src[i];
    for (int i = threadIdx.x; i < NIN * 8; i += 256)
        Ws[i] = W[i];
    __syncthreads();

    const float* x = &tile[threadIdx.x * NIN];
    float o[8] = {0, 0, 0, 0, 0, 0, 0, 0};
    #pragma unroll
    for (int c = 0; c < NIN; c++) {
        float xv = x[c];
        #pragma unroll
        for (int b = 0; b < 8; b++)
            o[b] = fmaf(xv, Ws[c * 8 + b], o[b]);
    }
    float4* op = (float4*)(out + (base + threadIdx.x) * 8);
    op[0] = make_float4(o[0], o[1], o[2], o[3]);
    op[1] = make_float4(o[4], o[5], o[6], o[7]);
}

__global__ void zero_kernel(float4* __restrict__ p, size_t n4)
{
    size_t i = (size_t)blockIdx.x * blockDim.x + threadIdx.x;
    if (i < n4) p[i] = make_float4(0.f, 0.f, 0.f, 0.f);
}

// ---------------------------------------------------------------------------
// Triplet gather/gate/scatter (16 lanes per triplet, vector red.add)
// ---------------------------------------------------------------------------
__global__ __launch_bounds__(256) void triplet_kernel(
    const int* __restrict__ expand_to_kj,
    const int* __restrict__ reduce_to_ji,
    const float* __restrict__ sbf8,
    const float* __restrict__ Wsbf2,
    const float* __restrict__ ang,
    float* __restrict__ agg)
{
    __shared__ float Ws[8 * 64];
    for (int i = threadIdx.x; i < 512; i += 256) Ws[i] = Wsbf2[i];
    __syncthreads();

    const int lane16 = threadIdx.x & 15;
    const size_t tIdx = ((size_t)blockIdx.x * 256 + threadIdx.x) >> 4;

    const int ekj = expand_to_kj[tIdx];
    const int eji = reduce_to_ji[tIdx];
    const float* s8 = sbf8 + tIdx * 8;

    float g0 = 0.f, g1 = 0.f, g2 = 0.f, g3 = 0.f;
    #pragma unroll
    for (int b = 0; b < 8; b++) {
        const float sb = __ldg(&s8[b]);
        const float* w = &Ws[b * 64 + lane16 * 4];
        g0 = fmaf(sb, w[0], g0);
        g1 = fmaf(sb, w[1], g1);
        g2 = fmaf(sb, w[2], g2);
        g3 = fmaf(sb, w[3], g3);
    }

    float4 a = __ldg((const float4*)(ang + (size_t)ekj * 64 + lane16 * 4));
    float vx = a.x * g0, vy = a.y * g1, vz = a.z * g2, vw = a.w * g3;

    float* dst = agg + (size_t)eji * 64 + lane16 * 4;
    asm volatile("red.global.add.v4.f32 [%0], {%1,%2,%3,%4};"
                 :: "l"(dst), "f"(vx), "f"(vy), "f"(vz), "f"(vw)
                 : "memory");
}

// ---------------------------------------------------------------------------
// Host orchestration
// ---------------------------------------------------------------------------
static inline int gemm_smem(int K) {
    return 4608 + 2 * (128 * (K + 8) * 2);
}

extern "C" void kernel_launch(void* const* d_in, const int* in_sizes, int n_in,
                              void* d_out, int out_size)
{
    const float* m_input = (const float*)d_in[0];
    const float* rbf     = (const float*)d_in[1];
    const float* sbf     = (const float*)d_in[2];
    const int*   expand  = (const int*)  d_in[3];
    const int*   reduce  = (const int*)  d_in[4];
    const float* W_kj    = (const float*)d_in[5];
    const float* b_kj    = (const float*)d_in[6];
    const float* W_rbf1  = (const float*)d_in[7];
    const float* W_rbf2  = (const float*)d_in[8];
    const float* W_sbf1  = (const float*)d_in[9];
    const float* W_sbf2  = (const float*)d_in[10];
    const float* W_down  = (const float*)d_in[11];
    const float* W_up    = (const float*)d_in[12];
    const float* W_ji    = (const float*)d_in[13];
    const float* b_ji    = (const float*)d_in[14];
    const float* W_res_b = (const float*)d_in[15];
    const float* b_res_b = (const float*)d_in[16];
    const float* W_final = (const float*)d_in[17];
    const float* b_final = (const float*)d_in[18];
    const float* W_res_a = (const float*)d_in[19];
    const float* b_res_a = (const float*)d_in[20];
    float* out = (float*)d_out;

    const int E = in_sizes[0] / 128;
    const int T = in_sizes[3];

    float *h1, *ang, *agg, *t, *m, *rbf8, *sbf8, *wb;
    cudaGetSymbolAddress((void**)&h1,   g_h1);
    cudaGetSymbolAddress((void**)&ang,  g_ang);
    cudaGetSymbolAddress((void**)&agg,  g_agg);
    cudaGetSymbolAddress((void**)&t,    g_t);
    cudaGetSymbolAddress((void**)&m,    g_m);
    cudaGetSymbolAddress((void**)&rbf8, g_rbf8);
    cudaGetSymbolAddress((void**)&sbf8, g_sbf8);
    cudaGetSymbolAddress((void**)&wb,   g_wb);

    cudaFuncSetAttribute(mma_gemm<128, 128, EP_SWISH>,
                         cudaFuncAttributeMaxDynamicSharedMemorySize, gemm_smem(128));
    cudaFuncSetAttribute(mma_gemm<128, 128, EP_SWISH_ADD>,
                         cudaFuncAttributeMaxDynamicSharedMemorySize, gemm_smem(128));
    cudaFuncSetAttribute(mma_gemm<128, 128, EP_SWISH_MULG>,
                         cudaFuncAttributeMaxDynamicSharedMemorySize, gemm_smem(128));
    cudaFuncSetAttribute(mma_gemm<64, 128, EP_SWISH>,
                         cudaFuncAttributeMaxDynamicSharedMemorySize, gemm_smem(128));
    cudaFuncSetAttribute(mma_gemm<128, 64, EP_SWISH>,
                         cudaFuncAttributeMaxDynamicSharedMemorySize, gemm_smem(64));

    // weight fragment buffer byte offsets
    char* wbb = (char*)wb;
    auto wat = [&](size_t off) { return (float*)(wbb + off); };
    const size_t OF_KJ = 0, OF_JI = 65536, OF_RB0 = 131072, OF_RB1 = 196608,
                 OF_FIN = 262144, OF_RA00 = 327680, OF_RA01 = 393216,
                 OF_RA10 = 458752, OF_RA11 = 524288,
                 OF_DOWN = 589824, OF_UP = 622592;

    wconv_kernel<<<16, 256>>>(W_kj,            wat(OF_KJ),   128, 128);
    wconv_kernel<<<16, 256>>>(W_ji,            wat(OF_JI),   128, 128);
    wconv_kernel<<<16, 256>>>(W_res_b,         wat(OF_RB0),  128, 128);
    wconv_kernel<<<16, 256>>>(W_res_b + 16384, wat(OF_RB1),  128, 128);
    wconv_kernel<<<16, 256>>>(W_final,         wat(OF_FIN),  128, 128);
    wconv_kernel<<<16, 256>>>(W_res_a,         wat(OF_RA00), 128, 128);
    wconv_kernel<<<16, 256>>>(W_res_a + 16384, wat(OF_RA01), 128, 128);
    wconv_kernel<<<16, 256>>>(W_res_a + 32768, wat(OF_RA10), 128, 128);
    wconv_kernel<<<16, 256>>>(W_res_a + 49152, wat(OF_RA11), 128, 128);
    wconv_kernel<<<16, 256>>>(W_down,          wat(OF_DOWN), 128, 64);
    wconv_kernel<<<16, 256>>>(W_up,            wat(OF_UP),   64, 128);

    const int GE = E / 128;   // 2048

    // 1. rbf8 = rbf @ W_rbf1
    proj8_kernel<6><<<E / 256, 256>>>(rbf, W_rbf1, rbf8);

    // 2. h1 = swish(m_input @ W_kj + b_kj) * (rbf8 @ W_rbf2)
    mma_gemm<128, 128, EP_SWISH_MULG><<<GE, 256, gemm_smem(128)>>>(
        m_input, (const uint32_t*)wat(OF_KJ), b_kj, W_rbf2, rbf8, h1);

    // 3. ang = swish(h1 @ W_down)
    mma_gemm<64, 128, EP_SWISH><<<GE, 256, gemm_smem(128)>>>(
        h1, (const uint32_t*)wat(OF_DOWN), nullptr, nullptr, nullptr, ang);

    // 4. sbf8 = sbf @ W_sbf1
    proj8_kernel<42><<<T / 256, 256>>>(sbf, W_sbf1, sbf8);

    // 5. agg = 0
    {
        size_t n4 = (size_t)E * 64 / 4;
        zero_kernel<<<(unsigned)((n4 + 255) / 256), 256>>>((float4*)agg, n4);
    }

    // 6. scatter
    triplet_kernel<<<(unsigned)((size_t)T * 16 / 256), 256>>>(
        expand, reduce, sbf8, W_sbf2, ang, agg);

    // 7. t = swish(agg @ W_up)
    mma_gemm<128, 64, EP_SWISH><<<GE, 256, gemm_smem(64)>>>(
        agg, (const uint32_t*)wat(OF_UP), nullptr, nullptr, nullptr, t);

    // 8. m = swish(m_input @ W_ji + b_ji) + t
    mma_gemm<128, 128, EP_SWISH_ADD><<<GE, 256, gemm_smem(128)>>>(
        m_input, (const uint32_t*)wat(OF_JI), b_ji, t, nullptr, m);

    // 9. residual before skip
    mma_gemm<128, 128, EP_SWISH><<<GE, 256, gemm_smem(128)>>>(
        m, (const uint32_t*)wat(OF_RB0), b_res_b, nullptr, nullptr, h1);
    mma_gemm<128, 128, EP_SWISH_ADD><<<GE, 256, gemm_smem(128)>>>(
        h1, (const uint32_t*)wat(OF_RB1), b_res_b + 128, m, nullptr, t);

    // 10. m = swish(t @ W_final + b_final) + m_input
    mma_gemm<128, 128, EP_SWISH_ADD><<<GE, 256, gemm_smem(128)>>>(
        t, (const uint32_t*)wat(OF_FIN), b_final, m_input, nullptr, m);

    // 11. residual after skip (2 layers)
    mma_gemm<128, 128, EP_SWISH><<<GE, 256, gemm_smem(128)>>>(
        m, (const uint32_t*)wat(OF_RA00), b_res_a, nullptr, nullptr, h1);
    mma_gemm<128, 128, EP_SWISH_ADD><<<GE, 256, gemm_smem(128)>>>(
        h1, (const uint32_t*)wat(OF_RA01), b_res_a + 128, m, nullptr, t);

    mma_gemm<128, 128, EP_SWISH><<<GE, 256, gemm_smem(128)>>>(
        t, (const uint32_t*)wat(OF_RA10), b_res_a + 256, nullptr, nullptr, h1);
    mma_gemm<128, 128, EP_SWISH_ADD><<<GE, 256, gemm_smem(128)>>>(
        h1, (const uint32_t*)wat(OF_RA11), b_res_a + 384, t, nullptr, out);
}